// round 8
// baseline (speedup 1.0000x reference)
#include <cuda_runtime.h>
#include <cstdint>

// LIF scan, two-pass to unmix DRAM read/write streams:
//   Pass 1: read x [B,T,N] f32, run recurrence, pack spikes to 1 bit/elem
//           (8 MB scratch) via warp ballots  -> ~pure-READ stream.
//   Pass 2: expand bits (L2-hot) to f32 {0,1} output -> ~pure-WRITE stream.

#define B_DIM 64
#define T_DIM 128
#define N_DIM 8192
#define N4_PER_B (N_DIM / 4)            // 2048 float4 per time-row
#define WCOLS (B_DIM * N4_PER_B / 32)   // 4096 warp-columns

// 128 t-steps x 4096 warp-cols x uint4 = 8 MB scratch (static, allowed)
__device__ uint4 g_spike_bits[T_DIM * WCOLS];

__global__ void __launch_bounds__(256) lif_pack_kernel(const float4* __restrict__ x) {
    const float V_TH = 1.0f;
    const float TAU  = 0.25f;

    int tid  = blockIdx.x * blockDim.x + threadIdx.x;  // 0 .. B*N/4-1
    int lane = tid & 31;
    int wcol = tid >> 5;                                // global warp-column
    int b    = tid >> 11;
    int n4   = tid & (N4_PER_B - 1);

    long base = (long)b * T_DIM * N4_PER_B + n4;

    float mx = 0.f, my = 0.f, mz = 0.f, mw = 0.f;

#pragma unroll 8
    for (int t = 0; t < T_DIM; ++t) {
        float4 v = x[base + (long)t * N4_PER_B];

        mx = TAU * mx + v.x;
        my = TAU * my + v.y;
        mz = TAU * mz + v.z;
        mw = TAU * mw + v.w;

        bool sx = mx > V_TH;
        bool sy = my > V_TH;
        bool sz = mz > V_TH;
        bool sw = mw > V_TH;

        mx = sx ? 0.0f : mx;
        my = sy ? 0.0f : my;
        mz = sz ? 0.0f : mz;
        mw = sw ? 0.0f : mw;

        unsigned bx = __ballot_sync(0xFFFFFFFFu, sx);
        unsigned by = __ballot_sync(0xFFFFFFFFu, sy);
        unsigned bz = __ballot_sync(0xFFFFFFFFu, sz);
        unsigned bw = __ballot_sync(0xFFFFFFFFu, sw);

        if (lane == 0)
            g_spike_bits[t * WCOLS + wcol] = make_uint4(bx, by, bz, bw);
    }
}

// Fully parallel over (b, t, n4): pure write stream, scratch reads hit L2.
__global__ void __launch_bounds__(256) lif_expand_kernel(float4* __restrict__ out) {
    int tid = blockIdx.x * blockDim.x + threadIdx.x;   // 0 .. B*T*N/4-1
    int n4  = tid & (N4_PER_B - 1);
    int t   = (tid >> 11) & (T_DIM - 1);
    int b   = tid >> 18;
    int lane = n4 & 31;
    int wcol = (b * N4_PER_B + n4) >> 5;

    uint4 w = g_spike_bits[t * WCOLS + wcol];          // broadcast within warp

    float4 s;
    s.x = ((w.x >> lane) & 1u) ? 1.0f : 0.0f;
    s.y = ((w.y >> lane) & 1u) ? 1.0f : 0.0f;
    s.z = ((w.z >> lane) & 1u) ? 1.0f : 0.0f;
    s.w = ((w.w >> lane) & 1u) ? 1.0f : 0.0f;

    out[(long)b * T_DIM * N4_PER_B + (long)t * N4_PER_B + n4] = s;
}

extern "C" void kernel_launch(void* const* d_in, const int* in_sizes, int n_in,
                              void* d_out, int out_size) {
    const float4* x = (const float4*)d_in[0];
    float4* out     = (float4*)d_out;

    {   // Pass 1: recurrence + bit-pack (read-dominated)
        int total = B_DIM * N4_PER_B;          // 131072 threads
        lif_pack_kernel<<<total / 256, 256>>>(x);
    }
    {   // Pass 2: expand bits to f32 (write-dominated)
        int total = B_DIM * T_DIM * N4_PER_B;  // 16777216 threads
        lif_expand_kernel<<<total / 256, 256>>>(out);
    }
}

// round 9
// speedup vs baseline: 1.0146x; 1.0146x over previous
#include <cuda_runtime.h>

// LIF scan: x [B, T, N] -> spikes [B, T, N]
//   mem = TAU*mem + x;  spike = (mem > V_TH);  mem = spike ? 0 : mem
// Single pass, float4 per thread (128-bit LDG/STG), streaming cache hints
// (.cs: every byte touched exactly once), block=128 / grid=1024 (best R3 cfg).

#define B_DIM 64
#define T_DIM 128
#define N_DIM 8192

__global__ void __launch_bounds__(128) lif_kernel(const float4* __restrict__ x,
                                                  float4* __restrict__ out) {
    const float V_TH = 1.0f;
    const float TAU  = 0.25f;

    const int n4_per_b = N_DIM / 4;                    // 2048 float4 per time-row
    int tid = blockIdx.x * blockDim.x + threadIdx.x;   // 0 .. B*N/4-1
    int b   = tid >> 11;                               // / 2048
    int n4  = tid & (n4_per_b - 1);

    long base = (long)b * T_DIM * n4_per_b + n4;

    float mx = 0.f, my = 0.f, mz = 0.f, mw = 0.f;

#pragma unroll 8
    for (int t = 0; t < T_DIM; ++t) {
        long idx = base + (long)t * n4_per_b;
        float4 v = __ldcs(&x[idx]);        // streaming: evict-first in L2

        mx = TAU * mx + v.x;
        my = TAU * my + v.y;
        mz = TAU * mz + v.z;
        mw = TAU * mw + v.w;

        float4 s;
        s.x = (mx > V_TH) ? 1.0f : 0.0f;
        s.y = (my > V_TH) ? 1.0f : 0.0f;
        s.z = (mz > V_TH) ? 1.0f : 0.0f;
        s.w = (mw > V_TH) ? 1.0f : 0.0f;

        mx = (s.x > 0.0f) ? 0.0f : mx;
        my = (s.y > 0.0f) ? 0.0f : my;
        mz = (s.z > 0.0f) ? 0.0f : mz;
        mw = (s.w > 0.0f) ? 0.0f : mw;

        __stcs(&out[idx], s);              // streaming store
    }
}

extern "C" void kernel_launch(void* const* d_in, const int* in_sizes, int n_in,
                              void* d_out, int out_size) {
    const float4* x = (const float4*)d_in[0];
    float4* out     = (float4*)d_out;

    int total_threads = B_DIM * (N_DIM / 4);   // 131072
    int block = 128;
    int grid  = total_threads / block;         // 1024
    lif_kernel<<<grid, block>>>(x, out);
}

// round 10
// speedup vs baseline: 1.1659x; 1.1492x over previous
#include <cuda_runtime.h>

// LIF scan: x [B, T, N] -> spikes [B, T, N]
//   mem = TAU*mem + x;  spike = (mem > V_TH);  mem = spike ? 0 : mem
// float4 per thread, default cache policy (hints regress on sm_103a),
// 16-deep load batches per t-chunk, block=256.
// At the measured mixed-R/W HBM ceiling (~6.2 TB/s): 512 MB compulsory
// traffic -> ~79 us kernel floor.

#define B_DIM 64
#define T_DIM 128
#define N_DIM 8192

__global__ void __launch_bounds__(256) lif_kernel(const float4* __restrict__ x,
                                                  float4* __restrict__ out) {
    const float V_TH = 1.0f;
    const float TAU  = 0.25f;

    const int n4_per_b = N_DIM / 4;                    // 2048 float4 per time-row
    int tid = blockIdx.x * blockDim.x + threadIdx.x;   // 0 .. B*N/4-1
    int b   = tid >> 11;                               // / 2048
    int n4  = tid & (n4_per_b - 1);

    long base = (long)b * T_DIM * n4_per_b + n4;

    float mx = 0.f, my = 0.f, mz = 0.f, mw = 0.f;

    const int U = 16;                                  // 8 chunks of 16 t-steps
#pragma unroll 1
    for (int tc = 0; tc < T_DIM; tc += U) {
        float4 v[U];
#pragma unroll
        for (int u = 0; u < U; ++u)
            v[u] = x[base + (long)(tc + u) * n4_per_b];

        float4 s[U];
#pragma unroll
        for (int u = 0; u < U; ++u) {
            mx = TAU * mx + v[u].x;
            my = TAU * my + v[u].y;
            mz = TAU * mz + v[u].z;
            mw = TAU * mw + v[u].w;

            s[u].x = (mx > V_TH) ? 1.0f : 0.0f;
            s[u].y = (my > V_TH) ? 1.0f : 0.0f;
            s[u].z = (mz > V_TH) ? 1.0f : 0.0f;
            s[u].w = (mw > V_TH) ? 1.0f : 0.0f;

            mx = (s[u].x > 0.0f) ? 0.0f : mx;
            my = (s[u].y > 0.0f) ? 0.0f : my;
            mz = (s[u].z > 0.0f) ? 0.0f : mz;
            mw = (s[u].w > 0.0f) ? 0.0f : mw;
        }

#pragma unroll
        for (int u = 0; u < U; ++u)
            out[base + (long)(tc + u) * n4_per_b] = s[u];
    }
}

extern "C" void kernel_launch(void* const* d_in, const int* in_sizes, int n_in,
                              void* d_out, int out_size) {
    const float4* x = (const float4*)d_in[0];
    float4* out     = (float4*)d_out;

    int total_threads = B_DIM * (N_DIM / 4);   // 131072
    int block = 256;
    int grid  = total_threads / block;         // 512
    lif_kernel<<<grid, block>>>(x, out);
}

// round 13
// speedup vs baseline: 1.1866x; 1.0177x over previous
#include <cuda_runtime.h>

// LIF scan: x [B, T, N] -> spikes [B, T, N]
//   mem = TAU*mem + x;  spike = (mem > V_TH);  mem = spike ? 0 : mem
// Final config: float4 per thread, block=128, plain unroll-8 time loop,
// default cache policy (.cs regresses ~30% on sm_103a; two-pass R/W
// unmixing also regresses). Measured mixed-R/W HBM ceiling ~6.2 TB/s;
// 512 MB compulsory traffic -> ~79 us kernel floor, which this kernel hits.
// 32-bit running-offset indexing: element index max = 64*128*2048 = 2^24,
// fits unsigned easily; address chain is one IADD per t-step.

#define B_DIM 64
#define T_DIM 128
#define N_DIM 8192

__global__ void __launch_bounds__(128) lif_kernel(const float4* __restrict__ x,
                                                  float4* __restrict__ out) {
    const float V_TH = 1.0f;
    const float TAU  = 0.25f;

    const unsigned n4_per_b = N_DIM / 4;                        // 2048
    unsigned tid = blockIdx.x * blockDim.x + threadIdx.x;       // 0 .. 131071
    unsigned b   = tid >> 11;
    unsigned n4  = tid & (n4_per_b - 1);

    unsigned idx = b * (T_DIM * n4_per_b) + n4;                 // running offset

    float mx = 0.f, my = 0.f, mz = 0.f, mw = 0.f;

#pragma unroll 8
    for (int t = 0; t < T_DIM; ++t, idx += n4_per_b) {
        float4 v = x[idx];

        mx = TAU * mx + v.x;
        my = TAU * my + v.y;
        mz = TAU * mz + v.z;
        mw = TAU * mw + v.w;

        float4 s;
        s.x = (mx > V_TH) ? 1.0f : 0.0f;
        s.y = (my > V_TH) ? 1.0f : 0.0f;
        s.z = (mz > V_TH) ? 1.0f : 0.0f;
        s.w = (mw > V_TH) ? 1.0f : 0.0f;

        mx = (s.x > 0.0f) ? 0.0f : mx;
        my = (s.y > 0.0f) ? 0.0f : my;
        mz = (s.z > 0.0f) ? 0.0f : mz;
        mw = (s.w > 0.0f) ? 0.0f : mw;

        out[idx] = s;
    }
}

extern "C" void kernel_launch(void* const* d_in, const int* in_sizes, int n_in,
                              void* d_out, int out_size) {
    const float4* x = (const float4*)d_in[0];
    float4* out     = (float4*)d_out;

    int total_threads = B_DIM * (N_DIM / 4);   // 131072
    int block = 128;
    int grid  = total_threads / block;         // 1024
    lif_kernel<<<grid, block>>>(x, out);
}

// round 17
// speedup vs baseline: 1.2306x; 1.0371x over previous
#include <cuda_runtime.h>

// LIF scan: x [B, T, N] -> spikes [B, T, N]
//   mem = TAU*mem + x;  spike = (mem > V_TH);  mem = spike ? 0 : mem
//
// FINAL: float4 per thread, block=128, 16-deep forced load batches
// (asm memory barrier), __launch_bounds__(128,5), default cache policy.
// Measured mixed-R/W HBM ceiling ~6.2 TB/s; 512 MB compulsory traffic
// -> ~80 us kernel floor. This config produced the best wall (90.27 us).
// Falsified alternatives: .cs hints (-30%), two-pass R/W unmixing (-20%),
// float2/2x threads (-25%), block=256 (tie/worse).

#define B_DIM 64
#define T_DIM 128
#define N_DIM 8192

__global__ void __launch_bounds__(128, 5) lif_kernel(const float4* __restrict__ x,
                                                     float4* __restrict__ out) {
    const float V_TH = 1.0f;
    const float TAU  = 0.25f;

    const unsigned n4_per_b = N_DIM / 4;                     // 2048
    unsigned tid = blockIdx.x * blockDim.x + threadIdx.x;    // 0 .. 131071
    unsigned b   = tid >> 11;
    unsigned n4  = tid & (n4_per_b - 1);

    unsigned base = b * (T_DIM * n4_per_b) + n4;             // running offset

    float mx = 0.f, my = 0.f, mz = 0.f, mw = 0.f;

    const int U = 16;                                        // 8 chunks of 16 t-steps
#pragma unroll 1
    for (int tc = 0; tc < T_DIM; tc += U, base += U * n4_per_b) {
        float4 v[U];
#pragma unroll
        for (int u = 0; u < U; ++u)
            v[u] = x[base + u * n4_per_b];

        // Compiler barrier: all 16 LDG.128s issue before any STG below.
        asm volatile("" ::: "memory");

#pragma unroll
        for (int u = 0; u < U; ++u) {
            mx = TAU * mx + v[u].x;
            my = TAU * my + v[u].y;
            mz = TAU * mz + v[u].z;
            mw = TAU * mw + v[u].w;

            float4 s;
            s.x = (mx > V_TH) ? 1.0f : 0.0f;
            s.y = (my > V_TH) ? 1.0f : 0.0f;
            s.z = (mz > V_TH) ? 1.0f : 0.0f;
            s.w = (mw > V_TH) ? 1.0f : 0.0f;

            mx = (s.x > 0.0f) ? 0.0f : mx;
            my = (s.y > 0.0f) ? 0.0f : my;
            mz = (s.z > 0.0f) ? 0.0f : mz;
            mw = (s.w > 0.0f) ? 0.0f : mw;

            out[base + u * n4_per_b] = s;
        }
    }
}

extern "C" void kernel_launch(void* const* d_in, const int* in_sizes, int n_in,
                              void* d_out, int out_size) {
    const float4* x = (const float4*)d_in[0];
    float4* out     = (float4*)d_out;

    int total_threads = B_DIM * (N_DIM / 4);   // 131072
    int block = 128;
    int grid  = total_threads / block;         // 1024
    lif_kernel<<<grid, block>>>(x, out);
}